// round 6
// baseline (speedup 1.0000x reference)
#include <cuda_runtime.h>
#include <cstdint>

// Problem constants (fixed shapes from setup_inputs)
#define B_   512
#define C_   100
#define F_   224
#define E_   8192
#define H_   4
#define I_   28
#define INPUTS_ (F_ * I_)          // 6272 == x_b cols, no padding needed
#define FE_  (F_ * E_)             // 1,835,008
#define FE4_ (FE_ / 4)             // 458,752

// Scratch (device globals: allocation-free per harness rules)
// negw[(f*E + e)*4 + w] : bit (c - 32w) set  <=>  table[c][f][e] < 0
__device__ uint32_t g_negw[F_ * E_ * 4];          // 29.36 MB, L2-resident
__device__ int4     g_hashes[B_ * F_];            // 1.8 MB

// ---------------------------------------------------------------------------
// Phase A: stream the 734MB table once (coalesced, evict-first) and pack
// per-(f,e) 100-bit negative masks. Each thread handles 4 consecutive e.
// ---------------------------------------------------------------------------
__global__ void __launch_bounds__(256)
build_negw_kernel(const float* __restrict__ table)
{
    int t = blockIdx.x * 256 + threadIdx.x;       // 0 .. FE_/4
    const float4* p = reinterpret_cast<const float4*>(table) + t;

    uint32_t a0[4] = {0,0,0,0};
    uint32_t a1[4] = {0,0,0,0};
    uint32_t a2[4] = {0,0,0,0};
    uint32_t a3[4] = {0,0,0,0};

    #pragma unroll
    for (int c = 0; c < C_; ++c) {
        float4 v = __ldcs(p + (size_t)c * FE4_);
        const uint32_t bit = 1u << (c & 31);
        const int w = c >> 5;                     // compile-time after unroll
        if (v.x < 0.0f) a0[w] |= bit;
        if (v.y < 0.0f) a1[w] |= bit;
        if (v.z < 0.0f) a2[w] |= bit;
        if (v.w < 0.0f) a3[w] |= bit;
    }

    uint4* out = reinterpret_cast<uint4*>(g_negw) + (size_t)t * 4;
    out[0] = make_uint4(a0[0], a0[1], a0[2], a0[3]);
    out[1] = make_uint4(a1[0], a1[1], a1[2], a1[3]);
    out[2] = make_uint4(a2[0], a2[1], a2[2], a2[3]);
    out[3] = make_uint4(a3[0], a3[1], a3[2], a3[3]);
}

// ---------------------------------------------------------------------------
// Phase B: H3 hashes. One block per batch row; x row staged in smem; each
// thread f does 28 branchless conditional XORs for the 4 hash functions.
// ---------------------------------------------------------------------------
__global__ void __launch_bounds__(256)
hash_kernel(const int* __restrict__ x_b,
            const int* __restrict__ input_order,
            const int* __restrict__ hash_values)
{
    __shared__ int s_x[INPUTS_];
    __shared__ int s_hv[H_ * I_];

    const int b = blockIdx.x;
    const int* xr = x_b + (size_t)b * INPUTS_;
    for (int j = threadIdx.x; j < INPUTS_; j += 256)
        s_x[j] = xr[j];
    if (threadIdx.x < H_ * I_)
        s_hv[threadIdx.x] = hash_values[threadIdx.x];
    __syncthreads();

    const int f = threadIdx.x;
    if (f < F_) {
        const int* ord = input_order + f * I_;
        int h0 = 0, h1 = 0, h2 = 0, h3 = 0;
        #pragma unroll
        for (int i = 0; i < I_; ++i) {
            const int m = -(s_x[ord[i]] != 0);    // all-ones if bit set
            h0 ^= s_hv[0 * I_ + i] & m;
            h1 ^= s_hv[1 * I_ + i] & m;
            h2 ^= s_hv[2 * I_ + i] & m;
            h3 ^= s_hv[3 * I_ + i] & m;
        }
        g_hashes[b * F_ + f] = make_int4(h0, h1, h2, h3);
    }
}

// ---------------------------------------------------------------------------
// Phase C: accumulate. Block = one batch row, thread = class c (128 threads,
// warp w owns word w of the 100-bit mask). All mask/hash loads are uniform
// per warp and hit the L2-resident 29MB structure.
// out[b][c] = bias[c] + F - 2 * #{ f : OR_h negmask(f, hash_h) has bit c }
// ---------------------------------------------------------------------------
__global__ void __launch_bounds__(128)
accum_kernel(const float* __restrict__ bias, float* __restrict__ out)
{
    const int b    = blockIdx.x;
    const int tid  = threadIdx.x;
    const int w    = tid >> 5;
    const int lane = tid & 31;

    const int4* hb = g_hashes + b * F_;
    int cnt = 0;

    #pragma unroll 4
    for (int f = 0; f < F_; ++f) {
        const int4 h = __ldg(&hb[f]);
        const uint32_t* base = g_negw + (size_t)f * (E_ * 4) + w;
        uint32_t m = base[(size_t)h.x * 4]
                   | base[(size_t)h.y * 4]
                   | base[(size_t)h.z * 4]
                   | base[(size_t)h.w * 4];
        cnt += (m >> lane) & 1;
    }

    if (tid < C_)
        out[b * C_ + tid] = bias[tid] + (float)(F_ - 2 * cnt);
}

// ---------------------------------------------------------------------------
// Launch. Input order per metadata: x_b, input_order, hash_values, table, bias
// ---------------------------------------------------------------------------
extern "C" void kernel_launch(void* const* d_in, const int* in_sizes, int n_in,
                              void* d_out, int out_size)
{
    const int*   x_b         = (const int*)  d_in[0];
    const int*   input_order = (const int*)  d_in[1];
    const int*   hash_values = (const int*)  d_in[2];
    const float* table       = (const float*)d_in[3];
    const float* bias        = (const float*)d_in[4];
    float*       out         = (float*)d_out;

    // Phase B (tiny, independent of A) first so it overlaps nothing critical
    hash_kernel<<<B_, 256>>>(x_b, input_order, hash_values);

    // Phase A: 734MB table stream -> 29MB sign-mask structure
    build_negw_kernel<<<FE4_ / 256, 256>>>(table);

    // Phase C: gather+accumulate from L2-hot masks
    accum_kernel<<<B_, 128>>>(bias, out);
}

// round 7
// speedup vs baseline: 1.2827x; 1.2827x over previous
#include <cuda_runtime.h>
#include <cstdint>

// Problem constants (fixed shapes from setup_inputs)
#define B_   512
#define C_   100
#define F_   224
#define E_   8192
#define H_   4
#define I_   28
#define INPUTS_ (F_ * I_)          // 6272 == x_b cols, no padding needed
#define FE_  (F_ * E_)             // 1,835,008
#define FE4_ (FE_ / 4)             // 458,752
#define BUILD_BLOCKS (FE4_ / 256)  // 1792
#define XWORDS_ (INPUTS_ / 32)     // 196

// Scratch (device globals: allocation-free per harness rules)
// negw[(f*E + e)*4 + w] : bit (c - 32w) set  <=>  table[c][f][e] < 0
__device__ uint32_t g_negw[F_ * E_ * 4];          // 29.36 MB, L2-resident
__device__ int4     g_hashes[B_ * F_];            // 1.8 MB

// ---------------------------------------------------------------------------
// Fused Phase A + B. Blocks [0, BUILD_BLOCKS) stream the 734MB table
// (coalesced float4, evict-first) and pack per-(f,e) 100-bit negative masks.
// Blocks [BUILD_BLOCKS, +512) compute the H3 hashes for one batch row each,
// hiding entirely under the build blocks' DRAM time.
// ---------------------------------------------------------------------------
__global__ void __launch_bounds__(256)
fused_build_hash_kernel(const float* __restrict__ table,
                        const int*   __restrict__ x_b,
                        const int*   __restrict__ input_order,
                        const int*   __restrict__ hash_values)
{
    __shared__ uint32_t s_xbits[XWORDS_];     // 784 B  (packed x row)
    __shared__ int      s_hv[H_ * I_];        // 448 B

    const int bid = blockIdx.x;

    if (bid < BUILD_BLOCKS) {
        // ---------------- build role ----------------
        const int t = bid * 256 + threadIdx.x;            // 0 .. FE4_-1
        const float4* p = reinterpret_cast<const float4*>(table) + t;

        uint32_t a0[4] = {0,0,0,0};
        uint32_t a1[4] = {0,0,0,0};
        uint32_t a2[4] = {0,0,0,0};
        uint32_t a3[4] = {0,0,0,0};

        #pragma unroll
        for (int c = 0; c < C_; ++c) {
            float4 v = __ldcs(p + (size_t)c * FE4_);
            const uint32_t bit = 1u << (c & 31);
            const int w = c >> 5;                         // compile-time
            if (v.x < 0.0f) a0[w] |= bit;
            if (v.y < 0.0f) a1[w] |= bit;
            if (v.z < 0.0f) a2[w] |= bit;
            if (v.w < 0.0f) a3[w] |= bit;
        }

        uint4* out = reinterpret_cast<uint4*>(g_negw) + (size_t)t * 4;
        out[0] = make_uint4(a0[0], a0[1], a0[2], a0[3]);
        out[1] = make_uint4(a1[0], a1[1], a1[2], a1[3]);
        out[2] = make_uint4(a2[0], a2[1], a2[2], a2[3]);
        out[3] = make_uint4(a3[0], a3[1], a3[2], a3[3]);
    } else {
        // ---------------- hash role ----------------
        const int b    = bid - BUILD_BLOCKS;
        const int tid  = threadIdx.x;
        const int wid  = tid >> 5;
        const int lane = tid & 31;

        // Ballot-pack the 6272-bit x row into 196 smem words.
        const int* xr = x_b + (size_t)b * INPUTS_;
        for (int j = wid; j < XWORDS_; j += 8) {
            int v = xr[j * 32 + lane];
            uint32_t bal = __ballot_sync(0xFFFFFFFFu, v != 0);
            if (lane == 0) s_xbits[j] = bal;
        }
        if (tid < H_ * I_)
            s_hv[tid] = hash_values[tid];
        __syncthreads();

        const int f = tid;
        if (f < F_) {
            const int* ord = input_order + f * I_;
            int h0 = 0, h1 = 0, h2 = 0, h3 = 0;
            #pragma unroll
            for (int i = 0; i < I_; ++i) {
                const int idx = __ldg(&ord[i]);
                const int m = -(int)((s_xbits[idx >> 5] >> (idx & 31)) & 1u);
                h0 ^= s_hv[0 * I_ + i] & m;
                h1 ^= s_hv[1 * I_ + i] & m;
                h2 ^= s_hv[2 * I_ + i] & m;
                h3 ^= s_hv[3 * I_ + i] & m;
            }
            g_hashes[b * F_ + f] = make_int4(h0, h1, h2, h3);
        }
    }
}

// ---------------------------------------------------------------------------
// Phase C: accumulate. Block = one batch row, 512 threads = 4 f-segments
// (56 filters each) x 128 class-lanes (warp w owns mask word w). All mask /
// hash loads are warp-uniform and hit the L2-resident 29MB structure.
// out[b][c] = bias[c] + F - 2 * #{ f : OR_h negmask(f, hash_h) has bit c }
// ---------------------------------------------------------------------------
__global__ void __launch_bounds__(512)
accum_kernel(const float* __restrict__ bias, float* __restrict__ out)
{
    __shared__ int s_cnt[512];

    const int b    = blockIdx.x;
    const int tid  = threadIdx.x;
    const int g    = tid >> 7;        // f-segment 0..3
    const int t    = tid & 127;       // class lane
    const int w    = t >> 5;          // mask word
    const int lane = t & 31;

    const int4* hb = g_hashes + b * F_;
    int cnt = 0;

    const int f0 = g * (F_ / 4);
    #pragma unroll 7
    for (int f = f0; f < f0 + F_ / 4; ++f) {
        const int4 h = __ldg(&hb[f]);
        const uint32_t* base = g_negw + (size_t)f * (E_ * 4) + w;
        uint32_t m = base[(size_t)h.x * 4]
                   | base[(size_t)h.y * 4]
                   | base[(size_t)h.z * 4]
                   | base[(size_t)h.w * 4];
        cnt += (m >> lane) & 1;
    }

    s_cnt[tid] = cnt;
    __syncthreads();

    if (tid < 128) {
        int total = s_cnt[tid] + s_cnt[tid + 128] + s_cnt[tid + 256] + s_cnt[tid + 384];
        if (tid < C_)
            out[b * C_ + tid] = bias[tid] + (float)(F_ - 2 * total);
    }
}

// ---------------------------------------------------------------------------
// Launch. Input order per metadata: x_b, input_order, hash_values, table, bias
// ---------------------------------------------------------------------------
extern "C" void kernel_launch(void* const* d_in, const int* in_sizes, int n_in,
                              void* d_out, int out_size)
{
    const int*   x_b         = (const int*)  d_in[0];
    const int*   input_order = (const int*)  d_in[1];
    const int*   hash_values = (const int*)  d_in[2];
    const float* table       = (const float*)d_in[3];
    const float* bias        = (const float*)d_in[4];
    float*       out         = (float*)d_out;

    // Phase A+B fused: table stream + sign-mask build, hash blocks in the tail
    fused_build_hash_kernel<<<BUILD_BLOCKS + B_, 256>>>(
        table, x_b, input_order, hash_values);

    // Phase C: gather+accumulate from L2-hot masks
    accum_kernel<<<B_, 512>>>(bias, out);
}

// round 8
// speedup vs baseline: 1.3568x; 1.0577x over previous
#include <cuda_runtime.h>
#include <cstdint>

// Problem constants (fixed shapes from setup_inputs)
#define B_   512
#define C_   100
#define F_   224
#define E_   8192
#define H_   4
#define I_   28
#define INPUTS_ (F_ * I_)          // 6272 == x_b cols, no padding needed
#define FE_  (F_ * E_)             // 1,835,008
#define FE4_ (FE_ / 4)             // 458,752
#define BUILD_BLOCKS (FE4_ / 256)  // 1792
#define XWORDS_ (INPUTS_ / 32)     // 196

// Scratch (device globals: allocation-free per harness rules)
// negw[(f*E + e)*4 + w] : bit (c - 32w) set  <=>  table[c][f][e] < 0
__device__ uint32_t g_negw[F_ * E_ * 4];          // 29.36 MB
__device__ int4     g_hashes[B_ * F_];            // 1.8 MB

// ---------------------------------------------------------------------------
// Fused Phase A + B. Blocks [0, BUILD_BLOCKS) stream the 734MB table
// (coalesced float4, evict-first) and pack per-(f,e) 100-bit negative masks.
// Blocks [BUILD_BLOCKS, +512) compute the H3 hashes for one batch row each,
// hiding entirely under the build blocks' DRAM time.
// ---------------------------------------------------------------------------
__global__ void __launch_bounds__(256)
fused_build_hash_kernel(const float* __restrict__ table,
                        const int*   __restrict__ x_b,
                        const int*   __restrict__ input_order,
                        const int*   __restrict__ hash_values)
{
    __shared__ uint32_t s_xbits[XWORDS_];     // 784 B  (packed x row)
    __shared__ int      s_hv[H_ * I_];        // 448 B

    const int bid = blockIdx.x;

    if (bid < BUILD_BLOCKS) {
        // ---------------- build role ----------------
        const int t = bid * 256 + threadIdx.x;            // 0 .. FE4_-1
        const float4* p = reinterpret_cast<const float4*>(table) + t;

        uint32_t a0[4] = {0,0,0,0};
        uint32_t a1[4] = {0,0,0,0};
        uint32_t a2[4] = {0,0,0,0};
        uint32_t a3[4] = {0,0,0,0};

        #pragma unroll
        for (int c = 0; c < C_; ++c) {
            float4 v = __ldcs(p + (size_t)c * FE4_);
            const uint32_t bit = 1u << (c & 31);
            const int w = c >> 5;                         // compile-time
            if (v.x < 0.0f) a0[w] |= bit;
            if (v.y < 0.0f) a1[w] |= bit;
            if (v.z < 0.0f) a2[w] |= bit;
            if (v.w < 0.0f) a3[w] |= bit;
        }

        uint4* out = reinterpret_cast<uint4*>(g_negw) + (size_t)t * 4;
        out[0] = make_uint4(a0[0], a0[1], a0[2], a0[3]);
        out[1] = make_uint4(a1[0], a1[1], a1[2], a1[3]);
        out[2] = make_uint4(a2[0], a2[1], a2[2], a2[3]);
        out[3] = make_uint4(a3[0], a3[1], a3[2], a3[3]);
    } else {
        // ---------------- hash role ----------------
        const int b    = bid - BUILD_BLOCKS;
        const int tid  = threadIdx.x;
        const int wid  = tid >> 5;
        const int lane = tid & 31;

        // Ballot-pack the 6272-bit x row into 196 smem words.
        const int* xr = x_b + (size_t)b * INPUTS_;
        for (int j = wid; j < XWORDS_; j += 8) {
            int v = xr[j * 32 + lane];
            uint32_t bal = __ballot_sync(0xFFFFFFFFu, v != 0);
            if (lane == 0) s_xbits[j] = bal;
        }
        if (tid < H_ * I_)
            s_hv[tid] = hash_values[tid];
        __syncthreads();

        const int f = tid;
        if (f < F_) {
            const int* ord = input_order + f * I_;
            int h0 = 0, h1 = 0, h2 = 0, h3 = 0;
            #pragma unroll
            for (int i = 0; i < I_; ++i) {
                const int idx = __ldg(&ord[i]);
                const int m = -(int)((s_xbits[idx >> 5] >> (idx & 31)) & 1u);
                h0 ^= s_hv[0 * I_ + i] & m;
                h1 ^= s_hv[1 * I_ + i] & m;
                h2 ^= s_hv[2 * I_ + i] & m;
                h3 ^= s_hv[3 * I_ + i] & m;
            }
            g_hashes[b * F_ + f] = make_int4(h0, h1, h2, h3);
        }
    }
}

// ---------------------------------------------------------------------------
// Phase C: accumulate. Block = one batch row, 16 warps = 16 f-segments of 14
// filters. Each hash lookup is ONE warp-uniform 16B uint4 load (full 128-bit
// class mask); lane extracts its 4 classes (lane + 32w) from the OR'd mask.
// 4x fewer L2/DRAM requests and 4x shorter dependency chains than the
// word-per-warp layout. Final smem reduce over the 16 warp partials.
// out[b][c] = bias[c] + F - 2 * #{ f : OR_h negmask(f, hash_h) has bit c }
// ---------------------------------------------------------------------------
#define SEG_ (F_ / 16)             // 14 filters per warp
#define RPAD_ 132                  // padded row for conflict-free reduce

__global__ void __launch_bounds__(512)
accum_kernel(const float* __restrict__ bias, float* __restrict__ out)
{
    __shared__ int s_cnt[16 * RPAD_];

    const int b    = blockIdx.x;
    const int tid  = threadIdx.x;
    const int wi   = tid >> 5;        // f-segment / warp id
    const int lane = tid & 31;

    const int4*  hb = g_hashes + b * F_;
    const uint4* nw = reinterpret_cast<const uint4*>(g_negw);

    int c0 = 0, c1 = 0, c2 = 0, c3 = 0;
    const int f0 = wi * SEG_;

    #pragma unroll
    for (int k = 0; k < SEG_; ++k) {
        const int  f = f0 + k;
        const int4 h = __ldg(&hb[f]);
        const uint4* base = nw + (size_t)f * E_;
        const uint4 ma = __ldg(&base[h.x]);
        const uint4 mb = __ldg(&base[h.y]);
        const uint4 mc = __ldg(&base[h.z]);
        const uint4 md = __ldg(&base[h.w]);
        const uint32_t mx = ma.x | mb.x | mc.x | md.x;
        const uint32_t my = ma.y | mb.y | mc.y | md.y;
        const uint32_t mz = ma.z | mb.z | mc.z | md.z;
        const uint32_t mw = ma.w | mb.w | mc.w | md.w;
        c0 += (mx >> lane) & 1;
        c1 += (my >> lane) & 1;
        c2 += (mz >> lane) & 1;
        c3 += (mw >> lane) & 1;
    }

    int* sr = s_cnt + wi * RPAD_;
    sr[lane]      = c0;
    sr[lane + 32] = c1;
    sr[lane + 64] = c2;
    sr[lane + 96] = c3;
    __syncthreads();

    if (tid < 128) {
        int total = 0;
        #pragma unroll
        for (int w = 0; w < 16; ++w)
            total += s_cnt[w * RPAD_ + tid];
        if (tid < C_)
            out[b * C_ + tid] = bias[tid] + (float)(F_ - 2 * total);
    }
}

// ---------------------------------------------------------------------------
// Launch. Input order per metadata: x_b, input_order, hash_values, table, bias
// ---------------------------------------------------------------------------
extern "C" void kernel_launch(void* const* d_in, const int* in_sizes, int n_in,
                              void* d_out, int out_size)
{
    const int*   x_b         = (const int*)  d_in[0];
    const int*   input_order = (const int*)  d_in[1];
    const int*   hash_values = (const int*)  d_in[2];
    const float* table       = (const float*)d_in[3];
    const float* bias        = (const float*)d_in[4];
    float*       out         = (float*)d_out;

    // Phase A+B fused: table stream + sign-mask build, hash blocks in the tail
    fused_build_hash_kernel<<<BUILD_BLOCKS + B_, 256>>>(
        table, x_b, input_order, hash_values);

    // Phase C: gather+accumulate from L2-hot masks
    accum_kernel<<<B_, 512>>>(bias, out);
}